// round 5
// baseline (speedup 1.0000x reference)
#include <cuda_runtime.h>
#include <math.h>

#define BB 64
#define PP 256
#define NN 4096
#define SPLITK 32
#define KC (NN / SPLITK)   // 128

// Scratch (no allocations allowed -> __device__ globals)
__device__ float g_cphi[BB * NN];
__device__ float g_sphi[BB * NN];
__device__ float g_cxi[PP * NN];
__device__ float g_sxi[PP * NN];
__device__ float g_mpart[SPLITK * BB * PP];
__device__ float g_w[BB * PP];

// ---------------------------------------------------------------------------
// Kernel 1: trig tables. sincos of phi (B*N) and xi (P*N).
// ---------------------------------------------------------------------------
__global__ __launch_bounds__(256) void trig_kernel(const float* __restrict__ phi,
                                                   const float* __restrict__ xi) {
    int i = blockIdx.x * blockDim.x + threadIdx.x;
    if (i < BB * NN) {
        float s, c;
        sincosf(phi[i], &s, &c);
        g_sphi[i] = s;
        g_cphi[i] = c;
    } else if (i < (BB + PP) * NN) {
        int j = i - BB * NN;
        float s, c;
        sincosf(xi[j], &s, &c);
        g_sxi[j] = s;
        g_cxi[j] = c;
    }
}

// ---------------------------------------------------------------------------
// Kernel 2: m[b,p] = sum_n cphi[b,n]*cxi[p,n] + sphi[b,n]*sxi[p,n]
// GEMM M=64(b), N=256(p), K=4096. Split-K into 32 chunks of 128.
// Block: 256 threads (16x16), tile 64b x 64p, micro-tile 4x4.
// grid = (P/64, SPLITK) = (4, 32) = 128 blocks.
// ---------------------------------------------------------------------------
__global__ __launch_bounds__(256) void mgemm_kernel() {
    __shared__ float Ac[64][33], As[64][33];  // [b][k]
    __shared__ float Bc[64][33], Bs[64][33];  // [p][k]

    int p0 = blockIdx.x * 64;
    int k0 = blockIdx.y * KC;
    int tid = threadIdx.x;
    int tx = tid & 15;   // p micro index
    int ty = tid >> 4;   // b micro index

    float acc[4][4] = {};

    for (int kk = 0; kk < KC; kk += 32) {
#pragma unroll
        for (int i = tid; i < 64 * 32; i += 256) {
            int r = i >> 5, c = i & 31;
            int gk = k0 + kk + c;
            Ac[r][c] = g_cphi[r * NN + gk];
            As[r][c] = g_sphi[r * NN + gk];
            Bc[r][c] = g_cxi[(p0 + r) * NN + gk];
            Bs[r][c] = g_sxi[(p0 + r) * NN + gk];
        }
        __syncthreads();
#pragma unroll
        for (int k = 0; k < 32; k++) {
            float a_c[4], a_s[4], b_c[4], b_s[4];
#pragma unroll
            for (int i = 0; i < 4; i++) {
                a_c[i] = Ac[ty * 4 + i][k];
                a_s[i] = As[ty * 4 + i][k];
            }
#pragma unroll
            for (int j = 0; j < 4; j++) {
                b_c[j] = Bc[tx * 4 + j][k];
                b_s[j] = Bs[tx * 4 + j][k];
            }
#pragma unroll
            for (int i = 0; i < 4; i++)
#pragma unroll
                for (int j = 0; j < 4; j++)
                    acc[i][j] += a_c[i] * b_c[j] + a_s[i] * b_s[j];
        }
        __syncthreads();
    }

    float* outp = g_mpart + blockIdx.y * (BB * PP);
#pragma unroll
    for (int i = 0; i < 4; i++)
#pragma unroll
        for (int j = 0; j < 4; j++)
            outp[(ty * 4 + i) * PP + p0 + tx * 4 + j] = acc[i][j];
}

// ---------------------------------------------------------------------------
// Kernel 3: reduce split-K partials, softmax over p (per b). BETA=1.
// grid = B blocks, 256 threads (one per p).
// ---------------------------------------------------------------------------
__global__ __launch_bounds__(256) void softmax_kernel() {
    __shared__ float red[256];
    int b = blockIdx.x;
    int p = threadIdx.x;

    float s = 0.f;
#pragma unroll
    for (int sp = 0; sp < SPLITK; sp++)
        s += g_mpart[sp * BB * PP + b * PP + p];

    float val = s * (1.0f / (float)NN);  // BETA * m / N

    red[p] = val;
    __syncthreads();
    for (int off = 128; off > 0; off >>= 1) {
        if (p < off) red[p] = fmaxf(red[p], red[p + off]);
        __syncthreads();
    }
    float mx = red[0];
    __syncthreads();

    float e = expf(val - mx);
    red[p] = e;
    __syncthreads();
    for (int off = 128; off > 0; off >>= 1) {
        if (p < off) red[p] += red[p + off];
        __syncthreads();
    }
    g_w[b * PP + p] = e / red[0];
}

// ---------------------------------------------------------------------------
// Kernel 4: coupling GEMM + epilogue.
//   Wc[b,n] = sum_p w[b,p]*cxi[p,n],  Ws[b,n] = sum_p w[b,p]*sxi[p,n]
//   out[b,n] = sphi*Wc - cphi*Ws + A*(sin(wt)*cphi - cos(wt)*sphi)
// GEMM M=64(b), N=4096(n), K=256(p). Block: tile 32b x 64n, 256 threads
// (16x16), micro 2b x 4n. grid = (N/64, B/32) = (64, 2) = 128 blocks.
// ---------------------------------------------------------------------------
__global__ __launch_bounds__(256) void coupling_kernel(const float* __restrict__ t,
                                                       float* __restrict__ out) {
    __shared__ float Wt[32][33];     // [b][p-chunk]
    __shared__ float4 Bc4[32][16];   // [p-chunk][n/4]
    __shared__ float4 Bs4[32][16];

    int n0 = blockIdx.x * 64;
    int b0 = blockIdx.y * 32;
    int tid = threadIdx.x;
    int tx = tid & 15;   // n micro index (x4)
    int ty = tid >> 4;   // b micro index (x2)

    float accC[2][4] = {};
    float accS[2][4] = {};

    for (int pk = 0; pk < PP; pk += 32) {
        {
            int r = tid >> 5, c = tid & 31;
#pragma unroll
            for (int rr = r; rr < 32; rr += 8)
                Wt[rr][c] = g_w[(b0 + rr) * PP + pk + c];
        }
#pragma unroll
        for (int i = tid; i < 32 * 16; i += 256) {
            int r = i >> 4, c = i & 15;
            Bc4[r][c] = *(const float4*)&g_cxi[(pk + r) * NN + n0 + c * 4];
            Bs4[r][c] = *(const float4*)&g_sxi[(pk + r) * NN + n0 + c * 4];
        }
        __syncthreads();
#pragma unroll
        for (int p = 0; p < 32; p++) {
            float4 bc = Bc4[p][tx];
            float4 bs = Bs4[p][tx];
            float w0 = Wt[ty * 2 + 0][p];
            float w1 = Wt[ty * 2 + 1][p];
            accC[0][0] += w0 * bc.x; accC[0][1] += w0 * bc.y;
            accC[0][2] += w0 * bc.z; accC[0][3] += w0 * bc.w;
            accC[1][0] += w1 * bc.x; accC[1][1] += w1 * bc.y;
            accC[1][2] += w1 * bc.z; accC[1][3] += w1 * bc.w;
            accS[0][0] += w0 * bs.x; accS[0][1] += w0 * bs.y;
            accS[0][2] += w0 * bs.z; accS[0][3] += w0 * bs.w;
            accS[1][0] += w1 * bs.x; accS[1][1] += w1 * bs.y;
            accS[1][2] += w1 * bs.z; accS[1][3] += w1 * bs.w;
        }
        __syncthreads();
    }

    // Epilogue
    float tv = t[0];
    float warg = 1256.6370614359172f * tv;  // OMEGA_ANC * t (fp32, matching ref)
    double sd, cd;
    sincos((double)warg, &sd, &cd);         // accurate regardless of fast-math
    float st = (float)sd, ct = (float)cd;

#pragma unroll
    for (int i = 0; i < 2; i++) {
        int b = b0 + ty * 2 + i;
        int base = b * NN + n0 + tx * 4;
        float4 sp = *(const float4*)&g_sphi[base];
        float4 cp = *(const float4*)&g_cphi[base];
        float4 o;
        o.x = sp.x * accC[i][0] - cp.x * accS[i][0] + 0.08f * (st * cp.x - ct * sp.x);
        o.y = sp.y * accC[i][1] - cp.y * accS[i][1] + 0.08f * (st * cp.y - ct * sp.y);
        o.z = sp.z * accC[i][2] - cp.z * accS[i][2] + 0.08f * (st * cp.z - ct * sp.z);
        o.w = sp.w * accC[i][3] - cp.w * accS[i][3] + 0.08f * (st * cp.w - ct * sp.w);
        *(float4*)&out[base] = o;
    }
}

// ---------------------------------------------------------------------------
extern "C" void kernel_launch(void* const* d_in, const int* in_sizes, int n_in,
                              void* d_out, int out_size) {
    const float* t = nullptr;
    const float* phi = nullptr;
    const float* xi = nullptr;
    for (int i = 0; i < n_in; i++) {
        if (in_sizes[i] == 1) t = (const float*)d_in[i];
        else if (in_sizes[i] == BB * NN) phi = (const float*)d_in[i];
        else if (in_sizes[i] == PP * NN) xi = (const float*)d_in[i];
    }
    float* out = (float*)d_out;

    trig_kernel<<<((BB + PP) * NN + 255) / 256, 256>>>(phi, xi);
    mgemm_kernel<<<dim3(PP / 64, SPLITK), 256>>>();
    softmax_kernel<<<BB, 256>>>();
    coupling_kernel<<<dim3(NN / 64, BB / 32), 256>>>(t, out);
}